// round 14
// baseline (speedup 1.0000x reference)
#include <cuda_runtime.h>
#include <cuda_fp16.h>

#define TSEQ    1024
#define NB      512
#define RMAX    7
#define NDIRBLK 74
#define NBLK    (2 * NDIRBLK)
#define VOCABP1 50001
#define LOG2E   1.4426950408889634f
#define HSTR    72    // hs16 row stride (halves), padded vs 64

// Precomputed zx table: zw[dir][token][gate] = emb[token] @ W_dir + b_dir
__device__ float g_zw[2][VOCABP1][256];
// final hidden states: [dir][batch][64]
__device__ float g_h[2 * NB * 64];

static __device__ __forceinline__ unsigned long long pk2(float lo, float hi) {
    unsigned long long r;
    asm("mov.b64 %0, {%1,%2};" : "=l"(r) : "f"(lo), "f"(hi));
    return r;
}
static __device__ __forceinline__ void upk2(unsigned long long v, float &lo, float &hi) {
    asm("mov.b64 {%0,%1}, %2;" : "=f"(lo), "=f"(hi) : "l"(v));
}
static __device__ __forceinline__ void ffma2(unsigned long long &d,
                                             unsigned long long a,
                                             unsigned long long b) {
    asm("fma.rn.f32x2 %0, %1, %2, %0;" : "+l"(d) : "l"(a), "l"(b));
}
static __device__ __forceinline__ float tanha(float x) {
    float r; asm("tanh.approx.f32 %0, %1;" : "=f"(r) : "f"(x)); return r;
}
static __device__ __forceinline__ float sigm_t(float x) {
    // sigmoid(x) = 0.5 + 0.5 * tanh(x/2)  -- 1 MUFU + FMAs
    return fmaf(0.5f, tanha(0.5f * x), 0.5f);
}
static __device__ __forceinline__ void hmma16816(float* d,
                                                 unsigned a0, unsigned a1,
                                                 unsigned a2, unsigned a3,
                                                 unsigned b0, unsigned b1) {
    asm volatile(
        "mma.sync.aligned.m16n8k16.row.col.f32.f16.f16.f32 "
        "{%0,%1,%2,%3}, {%4,%5,%6,%7}, {%8,%9}, {%0,%1,%2,%3};\n"
        : "+f"(d[0]), "+f"(d[1]), "+f"(d[2]), "+f"(d[3])
        : "r"(a0), "r"(a1), "r"(a2), "r"(a3), "r"(b0), "r"(b1));
}

// ============================================================================
// Phase 1: zw[dir][v][j] = sum_k emb[v][k] * W_dir[k][j] + b_dir[j]
// ============================================================================
extern "C" __global__ void __launch_bounds__(256, 2)
zw_kernel(const float* __restrict__ emb,
          const float* __restrict__ Wf, const float* __restrict__ bf,
          const float* __restrict__ Wb, const float* __restrict__ bb)
{
    __shared__ __align__(16) float ebuf[64][64];
    const int dir  = blockIdx.y;
    const int base = blockIdx.x * 64;
    const int j    = threadIdx.x;
    const float* W  = dir ? Wb : Wf;
    const float* bv = dir ? bb : bf;

    unsigned long long wreg[32];
#pragma unroll
    for (int p = 0; p < 32; p++)
        wreg[p] = pk2(W[(2 * p) * 256 + j], W[(2 * p + 1) * 256 + j]);
    const float bj = bv[j];

#pragma unroll
    for (int i = 0; i < 16; i++) {
        const int lin = i * 256 + j;
        const int r = lin >> 6, c = lin & 63;
        const int row = base + r;
        ebuf[r][c] = (row < VOCABP1) ? emb[(long long)row * 64 + c] : 0.f;
    }
    __syncthreads();

    float* outp = &g_zw[dir][0][0];
#pragma unroll 1
    for (int r = 0; r < 64; r++) {
        if (base + r >= VOCABP1) break;
        const ulonglong2* srow = (const ulonglong2*)(&ebuf[r][0]);
        unsigned long long a0 = 0ull, a1 = 0ull;
#pragma unroll
        for (int q = 0; q < 8; q++) {
            const ulonglong2 v0 = srow[2 * q];
            const ulonglong2 v1 = srow[2 * q + 1];
            ffma2(a0, v0.x, wreg[4 * q + 0]);
            ffma2(a1, v0.y, wreg[4 * q + 1]);
            ffma2(a0, v1.x, wreg[4 * q + 2]);
            ffma2(a1, v1.y, wreg[4 * q + 3]);
        }
        float p0, p1, q0, q1;
        upk2(a0, p0, p1);
        upk2(a1, q0, q1);
        outp[(long long)(base + r) * 256 + j] = bj + ((p0 + q0) + (p1 + q1));
    }
}

// ============================================================================
// Phase 2: recurrent h@U via transposed tensor-core MMA:  z^T = U^T @ h^T.
// 148 blocks x 512 threads (16 warps), ONE barrier per step.
// TRUE depth-2 zx prefetch: 3-slot rotating register ring (zA/zB/zC) with the
// time loop unrolled x3 so roles rotate by code position -- no end-of-step
// register copies (a copy would wait on the in-flight LDG scoreboard, which
// was R12's hidden serialization). Slot written at step t is read at t+2 and
// rewritten at t+3. Token ring: 8 smem slots, token for t+4 written at t.
// ============================================================================
extern "C" __global__ void __launch_bounds__(512, 1)
lstm_kernel(const void* __restrict__ xraw,
            const float* __restrict__ Uf, const float* __restrict__ Ub)
{
    __shared__ __align__(16) __half hs16[2][8][HSTR];  // fp16 hidden, double buf
    __shared__ int idxs[8][8];                         // token ids, 8-slot ring

    const int tid  = threadIdx.x;
    const int wid  = tid >> 5;
    const int lane = tid & 31;
    const int lq   = lane >> 2;        // 0..7
    const int lr   = lane & 3;         // 0..3
    const int g0   = lq >> 2;          // 0..1 : my "gate parity"

    const int dir   = (blockIdx.x >= NDIRBLK) ? 1 : 0;
    const int bslot = blockIdx.x - dir * NDIRBLK;
    const int base  = bslot * RMAX;
    const int nrows = min(RMAX, NB - base);

    const int uw     = wid * 4;              // unit group (4 units per warp)
    const int myunit = uw + (lq & 3);
    const int myrow  = 2 * lr + g0;          // stage C row (0..7)
    const int colA   = myunit + 64 * g0;     // z-col for c0/c1; +128 for c2/c3

    const int*       x32 = (const int*)xraw;
    const long long* x64 = (const long long*)xraw;
    const bool is64 = ((x32[1] | x32[3] | x32[5] | x32[7]) == 0);

    const float* U   = dir ? Ub : Uf;
    const float* zwd = &g_zw[dir][0][0];

    // ---- A fragments: U^T fp16, permanent in registers ----
    unsigned afr[4][4];
#pragma unroll
    for (int kt = 0; kt < 4; kt++) {
#pragma unroll
        for (int hh = 0; hh < 2; hh++) {
            const int k0 = kt * 16 + 2 * lr + 8 * hh;
            __half2 lo = __floats2half2_rn(U[k0 * 256 + colA],
                                           U[(k0 + 1) * 256 + colA]);
            __half2 hi = __floats2half2_rn(U[k0 * 256 + colA + 128],
                                           U[(k0 + 1) * 256 + colA + 128]);
            afr[kt][2 * hh]     = *(unsigned*)&lo;   // a0 (hh=0) / a2 (hh=1)
            afr[kt][2 * hh + 1] = *(unsigned*)&hi;   // a1 (hh=0) / a3 (hh=1)
        }
    }

    // ---- prologue: all ring slots defined (dead rows: zero everywhere) ----
    if (tid < 8) {
        if (tid < nrows) {
            const long long xb = (long long)(base + tid) * TSEQ;
#pragma unroll
            for (int q = 0; q < 4; q++) {
                const int tq = dir ? (TSEQ - 1 - q) : q;
                idxs[q][tid] = is64 ? (int)x64[xb + tq] : x32[xb + tq];
            }
        } else {
#pragma unroll
            for (int q = 0; q < 8; q++) idxs[q][tid] = 0;
        }
    }
    {
        unsigned* hz = (unsigned*)&hs16[0][0][0];
        const int nw = (2 * 8 * HSTR * 2) / 4;
        for (int i = tid; i < nw; i += 512) hz[i] = 0u;
    }
    __syncthreads();

    // zx ring: zA = zx(t), zB = zx(t+1), zC = prefetch target for t+2
    float zA[4], zB[4], zC[4];
    {
        const long long tA0 = idxs[0][2 * lr], tB0 = idxs[0][2 * lr + 1];
        zA[0] = zwd[tA0 * 256 + colA];
        zA[1] = zwd[tB0 * 256 + colA];
        zA[2] = zwd[tA0 * 256 + colA + 128];
        zA[3] = zwd[tB0 * 256 + colA + 128];
        const long long tA1 = idxs[1][2 * lr], tB1 = idxs[1][2 * lr + 1];
        zB[0] = zwd[tA1 * 256 + colA];
        zB[1] = zwd[tB1 * 256 + colA];
        zB[2] = zwd[tA1 * 256 + colA + 128];
        zB[3] = zwd[tB1 * 256 + colA + 128];
    }
    float hreg = 0.f, creg = 0.f;

    // One LSTM step: consumes ZU (zx for step T), prefetches zx for T+2
    // into ZP. No register copies -> the ZP LDGs have ~2 steps of slack.
#define LSTM_STEP(T, ZU, ZP)                                                   \
    do {                                                                       \
        const int t_ = (T);                                                    \
        const int p_ = t_ & 1;                                                 \
        const int m_ = idxs[t_ & 7][myrow];                                    \
        if (t_ + 2 < TSEQ) {                                                   \
            const long long tA_ = idxs[(t_ + 2) & 7][2 * lr];                  \
            const long long tB_ = idxs[(t_ + 2) & 7][2 * lr + 1];              \
            ZP[0] = zwd[tA_ * 256 + colA];                                     \
            ZP[1] = zwd[tB_ * 256 + colA];                                     \
            ZP[2] = zwd[tA_ * 256 + colA + 128];                               \
            ZP[3] = zwd[tB_ * 256 + colA + 128];                               \
        }                                                                      \
        if ((tid < nrows) && (t_ + 4 < TSEQ)) {                                \
            const int tn_ = dir ? (TSEQ - 1 - (t_ + 4)) : (t_ + 4);            \
            const long long xb_ = (long long)(base + tid) * TSEQ;              \
            idxs[(t_ + 4) & 7][tid] = is64 ? (int)x64[xb_ + tn_]               \
                                           : x32[xb_ + tn_];                   \
        }                                                                      \
        unsigned bf_[4][2];                                                    \
        _Pragma("unroll")                                                      \
        for (int kt = 0; kt < 4; kt++) {                                       \
            bf_[kt][0] = *(const unsigned*)&hs16[p_][lq][kt * 16 + 2 * lr];    \
            bf_[kt][1] = *(const unsigned*)&hs16[p_][lq][kt * 16 + 2 * lr + 8];\
        }                                                                      \
        float dA_[4] = {ZU[0], ZU[1], ZU[2], ZU[3]};                           \
        float dB_[4] = {0.f, 0.f, 0.f, 0.f};                                   \
        hmma16816(dA_, afr[0][0], afr[0][1], afr[0][2], afr[0][3],             \
                  bf_[0][0], bf_[0][1]);                                       \
        hmma16816(dB_, afr[2][0], afr[2][1], afr[2][2], afr[2][3],             \
                  bf_[2][0], bf_[2][1]);                                       \
        hmma16816(dA_, afr[1][0], afr[1][1], afr[1][2], afr[1][3],             \
                  bf_[1][0], bf_[1][1]);                                       \
        hmma16816(dB_, afr[3][0], afr[3][1], afr[3][2], afr[3][3],             \
                  bf_[3][0], bf_[3][1]);                                       \
        float d_[4];                                                           \
        _Pragma("unroll")                                                      \
        for (int i = 0; i < 4; i++) d_[i] = dA_[i] + dB_[i];                   \
        const float sendA_ = g0 ? d_[0] : d_[1];                               \
        const float sendB_ = g0 ? d_[2] : d_[3];                               \
        const float recvA_ = __shfl_xor_sync(0xffffffffu, sendA_, 16);         \
        const float recvB_ = __shfl_xor_sync(0xffffffffu, sendB_, 16);         \
        const float zown0_ = g0 ? d_[1] : d_[0];                               \
        const float zown2_ = g0 ? d_[3] : d_[2];                               \
        const float zi_ = g0 ? recvA_ : zown0_;                                \
        const float zf_ = g0 ? zown0_ : recvA_;                                \
        const float zg_ = g0 ? recvB_ : zown2_;                                \
        const float zo_ = g0 ? zown2_ : recvB_;                                \
        const float ig_ = sigm_t(zi_);                                         \
        const float fg_ = sigm_t(zf_);                                         \
        const float gg_ = tanha(zg_);                                          \
        const float og_ = sigm_t(zo_);                                         \
        const float cn_ = fmaf(fg_, creg, ig_ * gg_);                          \
        const float hn_ = og_ * tanha(cn_);                                    \
        if (m_ != 0) { creg = cn_; hreg = hn_; }                               \
        hs16[p_ ^ 1][myrow][myunit] = __float2half(hreg);                      \
        __syncthreads();                                                       \
    } while (0)

    // 1024 = 3*341 + 1: main loop covers t = 0..1022, tail step t = 1023.
#pragma unroll 1
    for (int t = 0; t < TSEQ - 1; t += 3) {
        LSTM_STEP(t,     zA, zC);
        LSTM_STEP(t + 1, zB, zA);
        LSTM_STEP(t + 2, zC, zB);
    }
    LSTM_STEP(TSEQ - 1, zA, zC);   // t=1023 uses zA (written at t=1021)
#undef LSTM_STEP

    if (myrow < nrows)
        g_h[(dir * NB + (base + myrow)) * 64 + myunit] = hreg;
}

// ============================================================================
// Head: out[b] = relu(concat(hf,hb) @ W1 + b1) @ W2 + b2
// ============================================================================
extern "C" __global__ void head_kernel(const float* __restrict__ W1,
                                       const float* __restrict__ b1,
                                       const float* __restrict__ W2,
                                       const float* __restrict__ b2,
                                       float* __restrict__ out)
{
    const int b = blockIdx.x;
    const int u = threadIdx.x;
    const float* hf = &g_h[b * 64];
    const float* hb = &g_h[(NB + b) * 64];
    float acc = b1[u];
#pragma unroll
    for (int k = 0; k < 64; k++) acc = fmaf(hf[k], W1[k * 32 + u], acc);
#pragma unroll
    for (int k = 0; k < 64; k++) acc = fmaf(hb[k], W1[(64 + k) * 32 + u], acc);
    float v = fmaxf(acc, 0.f) * W2[u];
#pragma unroll
    for (int off = 16; off > 0; off >>= 1)
        v += __shfl_xor_sync(0xffffffffu, v, off);
    if (u == 0) out[b] = v + b2[0];
}

extern "C" void kernel_launch(void* const* d_in, const int* in_sizes, int n_in,
                              void* d_out, int out_size)
{
    const void*  x   = d_in[0];
    const float* emb = (const float*)d_in[1];
    const float* Wf  = (const float*)d_in[2];
    const float* Uf  = (const float*)d_in[3];
    const float* bf  = (const float*)d_in[4];
    const float* Wb  = (const float*)d_in[5];
    const float* Ub  = (const float*)d_in[6];
    const float* bb  = (const float*)d_in[7];
    const float* W1  = (const float*)d_in[8];
    const float* b1  = (const float*)d_in[9];
    const float* W2  = (const float*)d_in[10];
    const float* b2  = (const float*)d_in[11];

    zw_kernel<<<dim3((VOCABP1 + 63) / 64, 2), 256>>>(emb, Wf, bf, Wb, bb);
    lstm_kernel<<<NBLK, 512>>>(x, Uf, Ub);
    head_kernel<<<NB, 32>>>(W1, b1, W2, b2, (float*)d_out);
}